// round 14
// baseline (speedup 1.0000x reference)
#include <cuda_runtime.h>
#include <cuda_fp16.h>

#define N_NODES  100000
#define N_EDGES  3200000
#define N_GRAPHS 512
#define F1 35
#define F2 128
#define KDIM 70
#define RPAD 64                         // fp16 row padded to 64 halves = 128B = 1 full line
#define APAD 48                         // agg fp16 row stride (halves); read linearly only
#define NBIN 98                         // dst bins of 1024 nodes
#define BCAP 36864                      // slots per bin (mean 32.8k + 22 sigma)
#define BIN_BLK (N_EDGES / 4 / 256)     // 3125 (4 edges/thread)

// ---------------- device scratch (zero-initialized at load) ----------------
__device__ int    d_off[N_NODES + 1];
__device__ int    d_bin_cur[NBIN];       // bin fill levels; reset by agg (idempotent)
__device__ unsigned long long d_ebuf[(long)NBIN * BCAP];  // (dst<<32|src) per bin
__device__ int    d_csr_src[N_EDGES];    // PRESCALED: src * 8 (uint4-row units)
__device__ __half d_a2[N_NODES * APAD];  // fp16 agg rows; halves 40..47 stay 0 forever
__device__ __half d_xh[N_NODES * RPAD];  // 128B-aligned fp16 feature rows; pads stay 0
__device__ int    d_gmax[N_GRAPHS * F2];

#define FMA_F32X2(d, a, b, c) \
    asm("fma.rn.f32x2 %0, %1, %2, %3;" : "=l"(d) : "l"(a), "l"(b), "l"(c))
#define PACK_F32X2(out, lo, hi) \
    asm("mov.b64 %0, {%1, %2};" : "=l"(out) : "f"(lo), "f"(hi))
#define UNPACK_F32X2(lo, hi, in) \
    asm("mov.b64 {%0, %1}, %2;" : "=f"(lo), "=f"(hi) : "l"(in))

__device__ __forceinline__ int fkey(float f) {
    int i = __float_as_int(f);
    return i >= 0 ? i : (i ^ 0x7FFFFFFF);
}

__device__ __forceinline__ unsigned hadd2u(unsigned a, unsigned b) {
    unsigned r;
    asm("add.rn.f16x2 %0, %1, %2;" : "=r"(r) : "r"(a), "r"(b));
    return r;
}

// m16n8k16 fp16 MMA, fp32 accumulate (row-major A, col-major B)
__device__ __forceinline__ void mma16816(float* d, const unsigned* a, const unsigned* b) {
    asm volatile(
        "mma.sync.aligned.m16n8k16.row.col.f32.f16.f16.f32 "
        "{%0,%1,%2,%3}, {%4,%5,%6,%7}, {%8,%9}, {%0,%1,%2,%3};\n"
        : "+f"(d[0]), "+f"(d[1]), "+f"(d[2]), "+f"(d[3])
        : "r"(a[0]), "r"(a[1]), "r"(a[2]), "r"(a[3]), "r"(b[0]), "r"(b[1]));
}

// ---------------- K0: conv(x -> fp16 rows) + gmax reset ----------------
__global__ void pre_kernel(const float* __restrict__ x) {
    int i = blockIdx.x * blockDim.x + threadIdx.x;   // half2 slot
    if (i < N_GRAPHS * F2) d_gmax[i] = (int)0x807FFFFFu;   // fkey(-inf)
    if (i < N_NODES * 32) {
        int n = i >> 5, c = i & 31;
        int f0 = 2 * c, f1 = 2 * c + 1;
        float v0 = (f0 < F1) ? x[n * F1 + f0] : 0.f;
        float v1 = (f1 < F1) ? x[n * F1 + f1] : 0.f;
        ((__half2*)d_xh)[i] = __floats2half2_rn(v0, v1);
    }
}

// ---------------- K1: bin pass — scatter (dst,src) records into 98 dst-range bins ----------------
__global__ __launch_bounds__(256) void bin_kernel(const int* __restrict__ src,
                                                  const int* __restrict__ dst) {
    __shared__ int hist[NBIN];
    __shared__ int sbase[NBIN];
    const int t = threadIdx.x;
    if (t < NBIN) hist[t] = 0;
    __syncthreads();

    const int i = blockIdx.x * 256 + t;              // int4 slot
    int4 s4 = __ldg(&((const int4*)src)[i]);
    int4 d4 = __ldg(&((const int4*)dst)[i]);
    int b0 = d4.x >> 10, b1 = d4.y >> 10, b2 = d4.z >> 10, b3 = d4.w >> 10;
    int r0 = atomicAdd(&hist[b0], 1);
    int r1 = atomicAdd(&hist[b1], 1);
    int r2 = atomicAdd(&hist[b2], 1);
    int r3 = atomicAdd(&hist[b3], 1);
    __syncthreads();

    if (t < NBIN && hist[t] > 0) sbase[t] = atomicAdd(&d_bin_cur[t], hist[t]);
    __syncthreads();

    d_ebuf[(long)b0 * BCAP + sbase[b0] + r0] = ((unsigned long long)(unsigned)d4.x << 32) | (unsigned)s4.x;
    d_ebuf[(long)b1 * BCAP + sbase[b1] + r1] = ((unsigned long long)(unsigned)d4.y << 32) | (unsigned)s4.y;
    d_ebuf[(long)b2 * BCAP + sbase[b2] + r2] = ((unsigned long long)(unsigned)d4.z << 32) | (unsigned)s4.z;
    d_ebuf[(long)b3 * BCAP + sbase[b3] + r3] = ((unsigned long long)(unsigned)d4.w << 32) | (unsigned)s4.w;
}

// ---------------- K2: sort pass — per-bin counting sort (smem atomics) + d_off ----------------
__global__ __launch_bounds__(1024) void sort_kernel() {
    __shared__ int cnt[1024];
    __shared__ int sws[32];
    __shared__ int sbins[NBIN];
    __shared__ int sbb;
    const int b = blockIdx.x, t = threadIdx.x;
    const int lane = t & 31, wid = t >> 5;

    cnt[t] = 0;
    if (t < NBIN) sbins[t] = d_bin_cur[t];
    __syncthreads();
    if (t == 0) {
        int s = 0;
        for (int j = 0; j < b; j++) s += sbins[j];
        sbb = s;
    }
    const int n_e = sbins[b];
    const unsigned long long* __restrict__ ebuf = d_ebuf + (long)b * BCAP;

    // phase A: per-node histogram (smem atomics)
    for (int i = t; i < n_e; i += 1024) {
        int ln = (int)(ebuf[i] >> 32) - (b << 10);
        atomicAdd(&cnt[ln], 1);
    }
    __syncthreads();

    // block-wide exclusive scan over cnt[1024]
    const int v = cnt[t];
    int incl = v;
#pragma unroll
    for (int o = 1; o < 32; o <<= 1) {
        int y = __shfl_up_sync(0xffffffffu, incl, o);
        if (lane >= o) incl += y;
    }
    if (lane == 31) sws[wid] = incl;
    __syncthreads();
    if (t < 32) {
        int xv = sws[t], xi = xv;
#pragma unroll
        for (int o = 1; o < 32; o <<= 1) {
            int y = __shfl_up_sync(0xffffffffu, xi, o);
            if (lane >= o) xi += y;
        }
        sws[t] = xi - xv;
    }
    __syncthreads();
    const int excl = sws[wid] + incl - v;

    const int gn = (b << 10) + t;
    if (gn <= N_NODES) d_off[gn] = sbb + excl;   // covers d_off[N_NODES] via last bin

    __syncthreads();
    cnt[t] = excl;                                // reuse as write cursors
    __syncthreads();

    // phase B: scatter src (prescaled) into CSR span (hot ~131KB region)
    for (int i = t; i < n_e; i += 1024) {
        unsigned long long ed = ebuf[i];
        int ln = (int)(ed >> 32) - (b << 10);
        int pos = sbb + atomicAdd(&cnt[ln], 1);
        d_csr_src[pos] = ((int)(unsigned)(ed & 0xffffffffu)) * 8;
    }
}

// ---------------- K3: mean aggregation: unpredicated quad loop + tail, HADD2 ----------------
// 8 lanes x 16B cover one 128B row exactly; 4 edge groups/warp.
// Also resets d_bin_cur for the next graph replay (idempotent; runs twice).
__global__ __launch_bounds__(256) void agg_kernel() {
    if (blockIdx.x == 0 && threadIdx.x < NBIN) d_bin_cur[threadIdx.x] = 0;
    int w = (blockIdx.x * blockDim.x + threadIdx.x) >> 5;
    int lane = threadIdx.x & 31;
    if (w >= N_NODES) return;
    int g = lane >> 3;           // edge group 0..3
    int p = lane & 7;            // 16B slice -> halves 8p..8p+7
    int beg = d_off[w], end = d_off[w + 1];
    int deg = end - beg;

    unsigned a0 = 0u, a1 = 0u, a2 = 0u, a3 = 0u;   // 4x half2 accumulators

    const uint4* __restrict__ xh4 = (const uint4*)d_xh;   // row = 8 uint4
    const int* __restrict__ csr = d_csr_src;              // prescaled (*8)

    int e = beg + g;
    int nq = deg >> 2;
#pragma unroll 4
    for (int q = 0; q < nq; q++, e += 4) {                // unpredicated main loop
        int s = __ldg(&csr[e]);
        uint4 v = __ldg(&xh4[s + p]);
        a0 = hadd2u(a0, v.x);
        a1 = hadd2u(a1, v.y);
        a2 = hadd2u(a2, v.z);
        a3 = hadd2u(a3, v.w);
    }
    int rem = deg & 3;
    if (g < rem) {                                        // predicated tail (<=3 edges)
        int s = __ldg(&csr[e]);
        uint4 v = __ldg(&xh4[s + p]);
        a0 = hadd2u(a0, v.x);
        a1 = hadd2u(a1, v.y);
        a2 = hadd2u(a2, v.z);
        a3 = hadd2u(a3, v.w);
    }

    // butterfly-reduce the 4 edge groups (xor 8, xor 16)
    a0 = hadd2u(a0, __shfl_xor_sync(0xffffffffu, a0, 8));
    a1 = hadd2u(a1, __shfl_xor_sync(0xffffffffu, a1, 8));
    a2 = hadd2u(a2, __shfl_xor_sync(0xffffffffu, a2, 8));
    a3 = hadd2u(a3, __shfl_xor_sync(0xffffffffu, a3, 8));
    a0 = hadd2u(a0, __shfl_xor_sync(0xffffffffu, a0, 16));
    a1 = hadd2u(a1, __shfl_xor_sync(0xffffffffu, a1, 16));
    a2 = hadd2u(a2, __shfl_xor_sync(0xffffffffu, a2, 16));
    a3 = hadd2u(a3, __shfl_xor_sync(0xffffffffu, a3, 16));

    if (lane < 5) {
        float inv = 1.0f / fmaxf((float)deg, 1.0f);
        float2 f0 = __half22float2(*(__half2*)&a0);
        float2 f1 = __half22float2(*(__half2*)&a1);
        float2 f2 = __half22float2(*(__half2*)&a2);
        float2 f3 = __half22float2(*(__half2*)&a3);
        __half2 h0 = __floats2half2_rn(f0.x * inv, f0.y * inv);
        __half2 h1 = __floats2half2_rn(f1.x * inv, f1.y * inv);
        __half2 h2 = __floats2half2_rn(f2.x * inv, f2.y * inv);
        __half2 h3 = __floats2half2_rn(f3.x * inv, f3.y * inv);
        uint4 u;
        u.x = *(unsigned*)&h0; u.y = *(unsigned*)&h1;
        u.z = *(unsigned*)&h2; u.w = *(unsigned*)&h3;
        ((uint4*)(d_a2 + (long)w * APAD))[lane] = u;   // halves 0..39 (35..39 are zeros)
    }
}

// ---------------- K4: lin1 fp32 FFMA2, out = relu([agg|x] @ W1 + b1) -> fp16 h1 rows ----------------
__global__ __launch_bounds__(256) void lin1_kernel(
    const float* __restrict__ xin, const float* __restrict__ Wl,
    const float* __restrict__ bl, const float* __restrict__ Wr)
{
    __shared__ __align__(16) float sAT[KDIM][36];
    __shared__ float sW[KDIM * F1];
    __shared__ float sbl[F1];

    const int tid = threadIdx.x;
    const int jt = tid & 31;
    const int mt = tid >> 5;
    const int base_n = blockIdx.x * 32;

    for (int idx = tid; idx < KDIM * F1; idx += 256) {
        int k = idx / F1, j = idx - k * F1;
        sW[idx] = (k < F1) ? Wl[k * F1 + j] : Wr[(k - F1) * F1 + j];
    }
    if (tid < F1) sbl[tid] = bl[tid];
    for (int idx = tid; idx < 32 * F1; idx += 256) {
        int m = idx & 31, k = idx >> 5;
        long n = base_n + m;
        sAT[k][m]      = __half2float(d_a2[n * APAD + k]);
        sAT[k + F1][m] = xin[n * F1 + k];
    }
    __syncthreads();

    unsigned long long acc2[2][2];
#pragma unroll
    for (int p = 0; p < 2; p++)
#pragma unroll
        for (int c = 0; c < 2; c++) acc2[p][c] = 0ULL;

#pragma unroll 2
    for (int k = 0; k < KDIM; k++) {
        float4 a4 = *(const float4*)&sAT[k][mt * 4];
        unsigned long long a01, a23;
        PACK_F32X2(a01, a4.x, a4.y);
        PACK_F32X2(a23, a4.z, a4.w);
#pragma unroll
        for (int c = 0; c < 2; c++) {
            int j = jt + 32 * c;
            float w = (j < F1) ? sW[k * F1 + j] : 0.f;
            unsigned long long ww;
            PACK_F32X2(ww, w, w);
            FMA_F32X2(acc2[0][c], a01, ww, acc2[0][c]);
            FMA_F32X2(acc2[1][c], a23, ww, acc2[1][c]);
        }
    }

    const int n0 = base_n + mt * 4;
    float v[4];
#pragma unroll
    for (int c = 0; c < 2; c++) {
        int j = jt + 32 * c;
        if (j < F1) {
            UNPACK_F32X2(v[0], v[1], acc2[0][c]);
            UNPACK_F32X2(v[2], v[3], acc2[1][c]);
#pragma unroll
            for (int r = 0; r < 4; r++) {
                float o = fmaxf(v[r] + sbl[j], 0.f);
                d_xh[(long)(n0 + r) * RPAD + j] = __float2half(o);
            }
        }
    }
}

// ---------------- K6: lin2 + max-pool: HMMA m16n8k16, 64 nodes/block ----------------
__global__ __launch_bounds__(256) void mma_pool_kernel(
    const float* __restrict__ Wl, const float* __restrict__ bl,
    const float* __restrict__ Wr, const int* __restrict__ batch)
{
    __shared__ __align__(16) __half sA[64 * 88];
    __shared__ __align__(16) __half sB[128 * 88];
    __shared__ float sbl[F2];
    __shared__ int   sgm[F2];

    const int tid = threadIdx.x;
    const int w = tid >> 5;
    const int lane = tid & 31;
    const int gid = lane >> 2;
    const int tig = lane & 3;
    const int base = blockIdx.x * 64;

    for (int idx = tid; idx < 64 * 80; idx += 256) {
        int m = idx / 80, k = idx - (idx / 80) * 80;
        long n = base + m;
        __half v = __ushort_as_half((unsigned short)0);
        if (n < N_NODES) {
            if (k < F1) v = d_a2[n * APAD + k];
            else if (k < KDIM) v = d_xh[n * RPAD + (k - F1)];
        }
        sA[m * 88 + k] = v;
    }
    for (int idx = tid; idx < 80 * F2; idx += 256) {
        int k = idx >> 7, n = idx & 127;
        float v = 0.f;
        if (k < F1) v = Wl[k * F2 + n];
        else if (k < KDIM) v = Wr[(k - F1) * F2 + n];
        sB[n * 88 + k] = __float2half(v);
    }
    if (tid < F2) { sbl[tid] = bl[tid]; sgm[tid] = (int)0x80000000; }
    __syncthreads();

    const int wm = w & 3;
    const int wn = (w >> 2) * 8;
    float acc[8][4];
#pragma unroll
    for (int nt = 0; nt < 8; nt++)
#pragma unroll
        for (int c = 0; c < 4; c++) acc[nt][c] = 0.f;

#pragma unroll
    for (int kc = 0; kc < 5; kc++) {
        const int k0 = kc * 16;
        unsigned a[4];
        const int ra = (wm * 16 + gid) * 88 + k0 + tig * 2;
        a[0] = *(const unsigned*)&sA[ra];
        a[1] = *(const unsigned*)&sA[ra + 8 * 88];
        a[2] = *(const unsigned*)&sA[ra + 8];
        a[3] = *(const unsigned*)&sA[ra + 8 * 88 + 8];
#pragma unroll
        for (int nt = 0; nt < 8; nt++) {
            unsigned b[2];
            const int rb = ((wn + nt) * 8 + gid) * 88 + k0 + tig * 2;
            b[0] = *(const unsigned*)&sB[rb];
            b[1] = *(const unsigned*)&sB[rb + 8];
            mma16816(acc[nt], a, b);
        }
    }

    const int r0 = base + wm * 16 + gid;
    const int r1 = r0 + 8;
    const bool full = (base + 63 < N_NODES);
    const int gfirst = batch[base];
    const bool single = full && (gfirst == batch[base + 63]);

    if (single) {
#pragma unroll
        for (int nt = 0; nt < 8; nt++) {
            int c0 = (wn + nt) * 8 + tig * 2;
            int k0v = max(fkey(acc[nt][0] + sbl[c0]),     fkey(acc[nt][2] + sbl[c0]));
            int k1v = max(fkey(acc[nt][1] + sbl[c0 + 1]), fkey(acc[nt][3] + sbl[c0 + 1]));
            atomicMax(&sgm[c0], k0v);
            atomicMax(&sgm[c0 + 1], k1v);
        }
        __syncthreads();
        if (tid < F2) atomicMax(&d_gmax[gfirst * F2 + tid], sgm[tid]);
    } else {
        int b0 = (r0 < N_NODES) ? batch[r0] : -1;
        int b1 = (r1 < N_NODES) ? batch[r1] : -1;
#pragma unroll
        for (int nt = 0; nt < 8; nt++) {
            int c0 = (wn + nt) * 8 + tig * 2;
            if (b0 >= 0) {
                atomicMax(&d_gmax[b0 * F2 + c0],     fkey(acc[nt][0] + sbl[c0]));
                atomicMax(&d_gmax[b0 * F2 + c0 + 1], fkey(acc[nt][1] + sbl[c0 + 1]));
            }
            if (b1 >= 0) {
                atomicMax(&d_gmax[b1 * F2 + c0],     fkey(acc[nt][2] + sbl[c0]));
                atomicMax(&d_gmax[b1 * F2 + c0 + 1], fkey(acc[nt][3] + sbl[c0 + 1]));
            }
        }
    }
}

// ---------------- K7: FC head ----------------
__global__ __launch_bounds__(128) void head_kernel(
    const float* __restrict__ Wg1, const float* __restrict__ bg1,
    const float* __restrict__ Wg2, const float* __restrict__ bg2,
    const float* __restrict__ Wo,  const float* __restrict__ bo,
    float* __restrict__ out)
{
    int g = blockIdx.x, j = threadIdx.x;
    __shared__ float r0[F2], r1[F2];
    __shared__ float wred[4];
    int key = d_gmax[g * F2 + j];
    key = key >= 0 ? key : (key ^ 0x7FFFFFFF);
    r0[j] = __int_as_float(key);
    __syncthreads();
    float acc = bg1[j];
#pragma unroll 8
    for (int k = 0; k < F2; k++) acc += r0[k] * Wg1[k * F2 + j];
    r1[j] = fmaxf(acc, 0.f);
    __syncthreads();
    acc = bg2[j];
#pragma unroll 8
    for (int k = 0; k < F2; k++) acc += r1[k] * Wg2[k * F2 + j];
    float v = fmaxf(acc, 0.f) * Wo[j];
#pragma unroll
    for (int s = 16; s > 0; s >>= 1) v += __shfl_down_sync(0xffffffffu, v, s);
    if ((j & 31) == 0) wred[j >> 5] = v;
    __syncthreads();
    if (j == 0) out[g] = wred[0] + wred[1] + wred[2] + wred[3] + bo[0];
}

// ---------------- launcher (8 kernels; agg1 at capture index 3) ----------------
extern "C" void kernel_launch(void* const* d_in, const int* in_sizes, int n_in,
                              void* d_out, int out_size) {
    const float* x    = (const float*)d_in[0];
    const int*   ei   = (const int*)d_in[1];
    const int*   bat  = (const int*)d_in[2];
    const float* Wl1  = (const float*)d_in[3];
    const float* bl1  = (const float*)d_in[4];
    const float* Wr1  = (const float*)d_in[5];
    const float* Wl2  = (const float*)d_in[6];
    const float* bl2  = (const float*)d_in[7];
    const float* Wr2  = (const float*)d_in[8];
    const float* Wg1  = (const float*)d_in[9];
    const float* bg1  = (const float*)d_in[10];
    const float* Wg2  = (const float*)d_in[11];
    const float* bg2  = (const float*)d_in[12];
    const float* Wo   = (const float*)d_in[13];
    const float* bo   = (const float*)d_in[14];
    float* out = (float*)d_out;

    const int* src = ei;
    const int* dst = ei + N_EDGES;

    pre_kernel<<<(N_NODES * 32 + 255) / 256, 256>>>(x);                 // 0: conv + gmax reset
    bin_kernel<<<BIN_BLK, 256>>>(src, dst);                             // 1: edge binning
    sort_kernel<<<NBIN, 1024>>>();                                      // 2: per-bin sort -> CSR + d_off

    agg_kernel<<<(N_NODES * 32 + 255) / 256, 256>>>();                  // 3 <- profiled (+ bin_cur reset)
    lin1_kernel<<<N_NODES / 32, 256>>>(x, Wl1, bl1, Wr1);               // 4

    agg_kernel<<<(N_NODES * 32 + 255) / 256, 256>>>();                  // 5
    mma_pool_kernel<<<(N_NODES + 63) / 64, 256>>>(Wl2, bl2, Wr2, bat);  // 6

    head_kernel<<<N_GRAPHS, F2>>>(Wg1, bg1, Wg2, bg2, Wo, bo, out);     // 7
}

// round 15
// speedup vs baseline: 1.1151x; 1.1151x over previous
#include <cuda_runtime.h>
#include <cuda_fp16.h>

#define N_NODES  100000
#define N_EDGES  3200000
#define N_GRAPHS 512
#define F1 35
#define F2 128
#define RPAD 64                         // fp16 row padded to 64 halves = 128B = 1 full line
#define APAD 48                         // agg fp16 row stride (halves); halves 35..47 stay 0
#define KMMA 80                         // MMA K: [agg 40 | h1 40]
#define NBIN 98                         // dst bins of 1024 nodes
#define BCAP 36864                      // slots per bin (mean 32.8k + 22 sigma)
#define BIN_BLK (N_EDGES / 4 / 256)     // 3125 (4 edges/thread)
#define CONV_BLK (N_NODES * 32 / 256)   // 12500
#define W2_BLK 20                       // 128*80/2 half2 = 5120 -> 20 blocks

// ---------------- device scratch (zero-initialized at load) ----------------
__device__ int    d_off[N_NODES + 1];
__device__ int    d_bin_cur[NBIN];       // bin fill levels; reset by agg (idempotent)
__device__ unsigned long long d_ebuf[(long)NBIN * BCAP];  // (dst<<32|src) per bin
__device__ int    d_csr_src[N_EDGES];    // PRESCALED: src * 8 (uint4-row units)
__device__ __half d_a2[N_NODES * APAD];  // fp16 agg rows; halves 35..47 zero
__device__ __half d_xh[N_NODES * RPAD];  // 128B-aligned fp16 feature rows; pads 35..63 zero
__device__ __half d_w2h[F2 * KMMA];      // fp16 W2^T rows: [Wl2 35|0 5|Wr2 35|0 5]
__device__ int    d_gmax[N_GRAPHS * F2];

#define FMA_F32X2(d, a, b, c) \
    asm("fma.rn.f32x2 %0, %1, %2, %3;" : "=l"(d) : "l"(a), "l"(b), "l"(c))
#define PACK_F32X2(out, lo, hi) \
    asm("mov.b64 %0, {%1, %2};" : "=l"(out) : "f"(lo), "f"(hi))
#define UNPACK_F32X2(lo, hi, in) \
    asm("mov.b64 {%0, %1}, %2;" : "=f"(lo), "=f"(hi) : "l"(in))

__device__ __forceinline__ int fkey(float f) {
    int i = __float_as_int(f);
    return i >= 0 ? i : (i ^ 0x7FFFFFFF);
}

__device__ __forceinline__ unsigned hadd2u(unsigned a, unsigned b) {
    unsigned r;
    asm("add.rn.f16x2 %0, %1, %2;" : "=r"(r) : "r"(a), "r"(b));
    return r;
}

// m16n8k16 fp16 MMA, fp32 accumulate (row-major A, col-major B)
__device__ __forceinline__ void mma16816(float* d, const unsigned* a, const unsigned* b) {
    asm volatile(
        "mma.sync.aligned.m16n8k16.row.col.f32.f16.f16.f32 "
        "{%0,%1,%2,%3}, {%4,%5,%6,%7}, {%8,%9}, {%0,%1,%2,%3};\n"
        : "+f"(d[0]), "+f"(d[1]), "+f"(d[2]), "+f"(d[3])
        : "r"(a[0]), "r"(a[1]), "r"(a[2]), "r"(a[3]), "r"(b[0]), "r"(b[1]));
}

// ---------------- K0: conv(x -> fp16 rows) + gmax reset + W2 fp16 prep ----------------
__global__ void pre_kernel(const float* __restrict__ x,
                           const float* __restrict__ Wl2, const float* __restrict__ Wr2) {
    int b = blockIdx.x, t = threadIdx.x;
    if (b < CONV_BLK) {
        int i = b * 256 + t;
        if (i < N_GRAPHS * F2) d_gmax[i] = (int)0x807FFFFFu;   // fkey(-inf)
        int n = i >> 5, c = i & 31;
        int f0 = 2 * c, f1 = 2 * c + 1;
        float v0 = (f0 < F1) ? x[n * F1 + f0] : 0.f;
        float v1 = (f1 < F1) ? x[n * F1 + f1] : 0.f;
        ((__half2*)d_xh)[i] = __floats2half2_rn(v0, v1);
    } else {
        int i = (b - CONV_BLK) * 256 + t;           // half2 slot in d_w2h
        if (i < F2 * KMMA / 2) {
            int h0 = 2 * i;
            int n = h0 / KMMA, k = h0 - n * KMMA;   // k even, k+1 same row
            float v0 = (k < F1) ? Wl2[k * F2 + n]
                     : ((k >= 40 && k < 40 + F1) ? Wr2[(k - 40) * F2 + n] : 0.f);
            int k1 = k + 1;
            float v1 = (k1 < F1) ? Wl2[k1 * F2 + n]
                     : ((k1 >= 40 && k1 < 40 + F1) ? Wr2[(k1 - 40) * F2 + n] : 0.f);
            ((__half2*)d_w2h)[i] = __floats2half2_rn(v0, v1);
        }
    }
}

// ---------------- K1: bin pass — scatter (dst,src) records into 98 dst-range bins ----------------
__global__ __launch_bounds__(256) void bin_kernel(const int* __restrict__ src,
                                                  const int* __restrict__ dst) {
    __shared__ int hist[NBIN];
    __shared__ int sbase[NBIN];
    const int t = threadIdx.x;
    if (t < NBIN) hist[t] = 0;
    __syncthreads();

    const int i = blockIdx.x * 256 + t;              // int4 slot
    int4 s4 = __ldg(&((const int4*)src)[i]);
    int4 d4 = __ldg(&((const int4*)dst)[i]);
    int b0 = d4.x >> 10, b1 = d4.y >> 10, b2 = d4.z >> 10, b3 = d4.w >> 10;
    int r0 = atomicAdd(&hist[b0], 1);
    int r1 = atomicAdd(&hist[b1], 1);
    int r2 = atomicAdd(&hist[b2], 1);
    int r3 = atomicAdd(&hist[b3], 1);
    __syncthreads();

    if (t < NBIN && hist[t] > 0) sbase[t] = atomicAdd(&d_bin_cur[t], hist[t]);
    __syncthreads();

    d_ebuf[(long)b0 * BCAP + sbase[b0] + r0] = ((unsigned long long)(unsigned)d4.x << 32) | (unsigned)s4.x;
    d_ebuf[(long)b1 * BCAP + sbase[b1] + r1] = ((unsigned long long)(unsigned)d4.y << 32) | (unsigned)s4.y;
    d_ebuf[(long)b2 * BCAP + sbase[b2] + r2] = ((unsigned long long)(unsigned)d4.z << 32) | (unsigned)s4.z;
    d_ebuf[(long)b3 * BCAP + sbase[b3] + r3] = ((unsigned long long)(unsigned)d4.w << 32) | (unsigned)s4.w;
}

// ---------------- K2: sort pass — per-bin counting sort (smem atomics) + d_off ----------------
__global__ __launch_bounds__(1024) void sort_kernel() {
    __shared__ int cnt[1024];
    __shared__ int sws[32];
    __shared__ int sbins[NBIN];
    __shared__ int sbb;
    const int b = blockIdx.x, t = threadIdx.x;
    const int lane = t & 31, wid = t >> 5;

    cnt[t] = 0;
    if (t < NBIN) sbins[t] = d_bin_cur[t];
    __syncthreads();
    if (t == 0) {
        int s = 0;
        for (int j = 0; j < b; j++) s += sbins[j];
        sbb = s;
    }
    const int n_e = sbins[b];
    const unsigned long long* __restrict__ ebuf = d_ebuf + (long)b * BCAP;

    for (int i = t; i < n_e; i += 1024) {
        int ln = (int)(ebuf[i] >> 32) - (b << 10);
        atomicAdd(&cnt[ln], 1);
    }
    __syncthreads();

    const int v = cnt[t];
    int incl = v;
#pragma unroll
    for (int o = 1; o < 32; o <<= 1) {
        int y = __shfl_up_sync(0xffffffffu, incl, o);
        if (lane >= o) incl += y;
    }
    if (lane == 31) sws[wid] = incl;
    __syncthreads();
    if (t < 32) {
        int xv = sws[t], xi = xv;
#pragma unroll
        for (int o = 1; o < 32; o <<= 1) {
            int y = __shfl_up_sync(0xffffffffu, xi, o);
            if (lane >= o) xi += y;
        }
        sws[t] = xi - xv;
    }
    __syncthreads();
    const int excl = sws[wid] + incl - v;

    const int gn = (b << 10) + t;
    if (gn <= N_NODES) d_off[gn] = sbb + excl;

    __syncthreads();
    cnt[t] = excl;
    __syncthreads();

    for (int i = t; i < n_e; i += 1024) {
        unsigned long long ed = ebuf[i];
        int ln = (int)(ed >> 32) - (b << 10);
        int pos = sbb + atomicAdd(&cnt[ln], 1);
        d_csr_src[pos] = ((int)(unsigned)(ed & 0xffffffffu)) * 8;
    }
}

// ---------------- K3: mean aggregation: 5 groups x 6 lanes, 3 sectors/edge, HADD2 ----------------
// 6 lanes x 16B cover the 96B payload of one 128B-aligned row (1 L1 wavefront, 3 L2 sectors).
// Also resets d_bin_cur for the next graph replay (idempotent; runs twice).
__global__ __launch_bounds__(256) void agg_kernel() {
    if (blockIdx.x == 0 && threadIdx.x < NBIN) d_bin_cur[threadIdx.x] = 0;
    int w = (blockIdx.x * blockDim.x + threadIdx.x) >> 5;
    int lane = threadIdx.x & 31;
    if (w >= N_NODES) return;
    int g = lane / 6;            // edge group 0..4 (lanes 30,31 -> 5, inactive)
    int p = lane - g * 6;        // 16B slice -> halves 8p..8p+7 (p 0..5)
    bool active = lane < 30;
    int beg = d_off[w], end = d_off[w + 1];
    int deg = end - beg;

    unsigned a0 = 0u, a1 = 0u, a2 = 0u, a3 = 0u;   // 4x half2 accumulators

    const uint4* __restrict__ xh4 = (const uint4*)d_xh;   // row = 8 uint4; read first 6
    const int* __restrict__ csr = d_csr_src;              // prescaled (*8)

    int e = beg + g;
    int nq = deg / 5;
#pragma unroll 4
    for (int q = 0; q < nq; q++, e += 5) {
        if (active) {
            int s = __ldg(&csr[e]);
            uint4 v = __ldg(&xh4[s + p]);
            a0 = hadd2u(a0, v.x);
            a1 = hadd2u(a1, v.y);
            a2 = hadd2u(a2, v.z);
            a3 = hadd2u(a3, v.w);
        }
    }
    int rem = deg - nq * 5;
    if (active && g < rem) {
        int s = __ldg(&csr[e]);
        uint4 v = __ldg(&xh4[s + p]);
        a0 = hadd2u(a0, v.x);
        a1 = hadd2u(a1, v.y);
        a2 = hadd2u(a2, v.z);
        a3 = hadd2u(a3, v.w);
    }

    // gather-sum the 5 groups (lanes p, p+6, p+12, p+18, p+24)
    unsigned t1, t2, t3, t4;
    t1 = __shfl_sync(0xffffffffu, a0, lane + 6);
    t2 = __shfl_sync(0xffffffffu, a0, lane + 12);
    t3 = __shfl_sync(0xffffffffu, a0, lane + 18);
    t4 = __shfl_sync(0xffffffffu, a0, lane + 24);
    a0 = hadd2u(hadd2u(hadd2u(a0, t1), hadd2u(t2, t3)), t4);
    t1 = __shfl_sync(0xffffffffu, a1, lane + 6);
    t2 = __shfl_sync(0xffffffffu, a1, lane + 12);
    t3 = __shfl_sync(0xffffffffu, a1, lane + 18);
    t4 = __shfl_sync(0xffffffffu, a1, lane + 24);
    a1 = hadd2u(hadd2u(hadd2u(a1, t1), hadd2u(t2, t3)), t4);
    t1 = __shfl_sync(0xffffffffu, a2, lane + 6);
    t2 = __shfl_sync(0xffffffffu, a2, lane + 12);
    t3 = __shfl_sync(0xffffffffu, a2, lane + 18);
    t4 = __shfl_sync(0xffffffffu, a2, lane + 24);
    a2 = hadd2u(hadd2u(hadd2u(a2, t1), hadd2u(t2, t3)), t4);
    t1 = __shfl_sync(0xffffffffu, a3, lane + 6);
    t2 = __shfl_sync(0xffffffffu, a3, lane + 12);
    t3 = __shfl_sync(0xffffffffu, a3, lane + 18);
    t4 = __shfl_sync(0xffffffffu, a3, lane + 24);
    a3 = hadd2u(hadd2u(hadd2u(a3, t1), hadd2u(t2, t3)), t4);

    if (lane < 5) {
        float inv = 1.0f / fmaxf((float)deg, 1.0f);
        float2 f0 = __half22float2(*(__half2*)&a0);
        float2 f1 = __half22float2(*(__half2*)&a1);
        float2 f2 = __half22float2(*(__half2*)&a2);
        float2 f3 = __half22float2(*(__half2*)&a3);
        __half2 h0 = __floats2half2_rn(f0.x * inv, f0.y * inv);
        __half2 h1 = __floats2half2_rn(f1.x * inv, f1.y * inv);
        __half2 h2 = __floats2half2_rn(f2.x * inv, f2.y * inv);
        __half2 h3 = __floats2half2_rn(f3.x * inv, f3.y * inv);
        uint4 u;
        u.x = *(unsigned*)&h0; u.y = *(unsigned*)&h1;
        u.z = *(unsigned*)&h2; u.w = *(unsigned*)&h3;
        ((uint4*)(d_a2 + (long)w * APAD))[lane] = u;   // halves 0..39 (35..39 zeros)
    }
}

// ---------------- K4: lin1 fp32 FFMA2, out = relu([agg|x] @ W1 + b1) -> fp16 h1 rows ----------------
__global__ __launch_bounds__(256) void lin1_kernel(
    const float* __restrict__ xin, const float* __restrict__ Wl,
    const float* __restrict__ bl, const float* __restrict__ Wr)
{
    __shared__ __align__(16) float sAT[2 * F1][36];
    __shared__ float sW[2 * F1 * F1];
    __shared__ float sbl[F1];

    const int tid = threadIdx.x;
    const int jt = tid & 31;
    const int mt = tid >> 5;
    const int base_n = blockIdx.x * 32;

    for (int idx = tid; idx < 2 * F1 * F1; idx += 256) {
        int k = idx / F1, j = idx - k * F1;
        sW[idx] = (k < F1) ? Wl[k * F1 + j] : Wr[(k - F1) * F1 + j];
    }
    if (tid < F1) sbl[tid] = bl[tid];
    for (int idx = tid; idx < 32 * F1; idx += 256) {
        int m = idx & 31, k = idx >> 5;
        long n = base_n + m;
        sAT[k][m]      = __half2float(d_a2[n * APAD + k]);
        sAT[k + F1][m] = xin[n * F1 + k];
    }
    __syncthreads();

    unsigned long long acc2[2][2];
#pragma unroll
    for (int p = 0; p < 2; p++)
#pragma unroll
        for (int c = 0; c < 2; c++) acc2[p][c] = 0ULL;

#pragma unroll 2
    for (int k = 0; k < 2 * F1; k++) {
        float4 a4 = *(const float4*)&sAT[k][mt * 4];
        unsigned long long a01, a23;
        PACK_F32X2(a01, a4.x, a4.y);
        PACK_F32X2(a23, a4.z, a4.w);
#pragma unroll
        for (int c = 0; c < 2; c++) {
            int j = jt + 32 * c;
            float w = (j < F1) ? sW[k * F1 + j] : 0.f;
            unsigned long long ww;
            PACK_F32X2(ww, w, w);
            FMA_F32X2(acc2[0][c], a01, ww, acc2[0][c]);
            FMA_F32X2(acc2[1][c], a23, ww, acc2[1][c]);
        }
    }

    const int n0 = base_n + mt * 4;
    float v[4];
#pragma unroll
    for (int c = 0; c < 2; c++) {
        int j = jt + 32 * c;
        if (j < F1) {
            UNPACK_F32X2(v[0], v[1], acc2[0][c]);
            UNPACK_F32X2(v[2], v[3], acc2[1][c]);
#pragma unroll
            for (int r = 0; r < 4; r++) {
                float o = fmaxf(v[r] + sbl[j], 0.f);
                d_xh[(long)(n0 + r) * RPAD + j] = __float2half(o);
            }
        }
    }
}

// ---------------- K6: lin2 + max-pool: HMMA m16n8k16, K=80, vectorized fills ----------------
__global__ __launch_bounds__(256) void mma_pool_kernel(
    const float* __restrict__ bl, const int* __restrict__ batch)
{
    __shared__ __align__(16) __half sA[64 * 88];
    __shared__ __align__(16) __half sB[128 * 88];
    __shared__ float sbl[F2];
    __shared__ int   sgm[F2];

    const int tid = threadIdx.x;
    const int w = tid >> 5;
    const int lane = tid & 31;
    const int gid = lane >> 2;
    const int tig = lane & 3;
    const int base = blockIdx.x * 64;

    // sA: [agg 40h | h1 40h] per row, 10 uint4 loads per row
    const uint4* __restrict__ a2v = (const uint4*)d_a2;   // row = 6 uint4 (use first 5)
    const uint4* __restrict__ xhv = (const uint4*)d_xh;   // row = 8 uint4 (use first 5)
    for (int i = tid; i < 64 * 10; i += 256) {
        int m = i / 10, j = i - (i / 10) * 10;
        long n = base + m;
        uint4 v = make_uint4(0u, 0u, 0u, 0u);
        if (n < N_NODES) v = (j < 5) ? a2v[n * 6 + j] : xhv[n * 8 + (j - 5)];
        *(uint4*)&sA[m * 88 + j * 8] = v;
    }
    // sB from prepped fp16 W2 table: 10 uint4 per row
    const uint4* __restrict__ wv = (const uint4*)d_w2h;   // row = 10 uint4
    for (int i = tid; i < 128 * 10; i += 256) {
        int n = i / 10, j = i - (i / 10) * 10;
        *(uint4*)&sB[n * 88 + j * 8] = wv[n * 10 + j];
    }
    if (tid < F2) { sbl[tid] = bl[tid]; sgm[tid] = (int)0x80000000; }
    __syncthreads();

    const int wm = w & 3;
    const int wn = (w >> 2) * 8;
    float acc[8][4];
#pragma unroll
    for (int nt = 0; nt < 8; nt++)
#pragma unroll
        for (int c = 0; c < 4; c++) acc[nt][c] = 0.f;

#pragma unroll
    for (int kc = 0; kc < 5; kc++) {
        const int k0 = kc * 16;
        unsigned a[4];
        const int ra = (wm * 16 + gid) * 88 + k0 + tig * 2;
        a[0] = *(const unsigned*)&sA[ra];
        a[1] = *(const unsigned*)&sA[ra + 8 * 88];
        a[2] = *(const unsigned*)&sA[ra + 8];
        a[3] = *(const unsigned*)&sA[ra + 8 * 88 + 8];
#pragma unroll
        for (int nt = 0; nt < 8; nt++) {
            unsigned b[2];
            const int rb = ((wn + nt) * 8 + gid) * 88 + k0 + tig * 2;
            b[0] = *(const unsigned*)&sB[rb];
            b[1] = *(const unsigned*)&sB[rb + 8];
            mma16816(acc[nt], a, b);
        }
    }

    const int r0 = base + wm * 16 + gid;
    const int r1 = r0 + 8;
    const bool full = (base + 63 < N_NODES);
    const int gfirst = batch[base];
    const bool single = full && (gfirst == batch[base + 63]);

    if (single) {
#pragma unroll
        for (int nt = 0; nt < 8; nt++) {
            int c0 = (wn + nt) * 8 + tig * 2;
            int k0v = max(fkey(acc[nt][0] + sbl[c0]),     fkey(acc[nt][2] + sbl[c0]));
            int k1v = max(fkey(acc[nt][1] + sbl[c0 + 1]), fkey(acc[nt][3] + sbl[c0 + 1]));
            atomicMax(&sgm[c0], k0v);
            atomicMax(&sgm[c0 + 1], k1v);
        }
        __syncthreads();
        if (tid < F2) atomicMax(&d_gmax[gfirst * F2 + tid], sgm[tid]);
    } else {
        int b0 = (r0 < N_NODES) ? batch[r0] : -1;
        int b1 = (r1 < N_NODES) ? batch[r1] : -1;
#pragma unroll
        for (int nt = 0; nt < 8; nt++) {
            int c0 = (wn + nt) * 8 + tig * 2;
            if (b0 >= 0) {
                atomicMax(&d_gmax[b0 * F2 + c0],     fkey(acc[nt][0] + sbl[c0]));
                atomicMax(&d_gmax[b0 * F2 + c0 + 1], fkey(acc[nt][1] + sbl[c0 + 1]));
            }
            if (b1 >= 0) {
                atomicMax(&d_gmax[b1 * F2 + c0],     fkey(acc[nt][2] + sbl[c0]));
                atomicMax(&d_gmax[b1 * F2 + c0 + 1], fkey(acc[nt][3] + sbl[c0 + 1]));
            }
        }
    }
}

// ---------------- K7: FC head ----------------
__global__ __launch_bounds__(128) void head_kernel(
    const float* __restrict__ Wg1, const float* __restrict__ bg1,
    const float* __restrict__ Wg2, const float* __restrict__ bg2,
    const float* __restrict__ Wo,  const float* __restrict__ bo,
    float* __restrict__ out)
{
    int g = blockIdx.x, j = threadIdx.x;
    __shared__ float r0[F2], r1[F2];
    __shared__ float wred[4];
    int key = d_gmax[g * F2 + j];
    key = key >= 0 ? key : (key ^ 0x7FFFFFFF);
    r0[j] = __int_as_float(key);
    __syncthreads();
    float acc = bg1[j];
#pragma unroll 8
    for (int k = 0; k < F2; k++) acc += r0[k] * Wg1[k * F2 + j];
    r1[j] = fmaxf(acc, 0.f);
    __syncthreads();
    acc = bg2[j];
#pragma unroll 8
    for (int k = 0; k < F2; k++) acc += r1[k] * Wg2[k * F2 + j];
    float v = fmaxf(acc, 0.f) * Wo[j];
#pragma unroll
    for (int s = 16; s > 0; s >>= 1) v += __shfl_down_sync(0xffffffffu, v, s);
    if ((j & 31) == 0) wred[j >> 5] = v;
    __syncthreads();
    if (j == 0) out[g] = wred[0] + wred[1] + wred[2] + wred[3] + bo[0];
}

// ---------------- launcher (8 kernels; agg1 at capture index 3) ----------------
extern "C" void kernel_launch(void* const* d_in, const int* in_sizes, int n_in,
                              void* d_out, int out_size) {
    const float* x    = (const float*)d_in[0];
    const int*   ei   = (const int*)d_in[1];
    const int*   bat  = (const int*)d_in[2];
    const float* Wl1  = (const float*)d_in[3];
    const float* bl1  = (const float*)d_in[4];
    const float* Wr1  = (const float*)d_in[5];
    const float* Wl2  = (const float*)d_in[6];
    const float* bl2  = (const float*)d_in[7];
    const float* Wr2  = (const float*)d_in[8];
    const float* Wg1  = (const float*)d_in[9];
    const float* bg1  = (const float*)d_in[10];
    const float* Wg2  = (const float*)d_in[11];
    const float* bg2  = (const float*)d_in[12];
    const float* Wo   = (const float*)d_in[13];
    const float* bo   = (const float*)d_in[14];
    float* out = (float*)d_out;

    const int* src = ei;
    const int* dst = ei + N_EDGES;

    pre_kernel<<<CONV_BLK + W2_BLK, 256>>>(x, Wl2, Wr2);                // 0
    bin_kernel<<<BIN_BLK, 256>>>(src, dst);                             // 1
    sort_kernel<<<NBIN, 1024>>>();                                      // 2

    agg_kernel<<<(N_NODES * 32 + 255) / 256, 256>>>();                  // 3 <- profiled
    lin1_kernel<<<N_NODES / 32, 256>>>(x, Wl1, bl1, Wr1);               // 4

    agg_kernel<<<(N_NODES * 32 + 255) / 256, 256>>>();                  // 5
    mma_pool_kernel<<<(N_NODES + 63) / 64, 256>>>(bl2, bat);            // 6

    head_kernel<<<N_GRAPHS, F2>>>(Wg1, bg1, Wg2, bg2, Wo, bo, out);     // 7
}

// round 16
// speedup vs baseline: 1.1553x; 1.0360x over previous
#include <cuda_runtime.h>
#include <cuda_fp16.h>

#define N_NODES  100000
#define N_EDGES  3200000
#define N_GRAPHS 512
#define F1 35
#define F2 128
#define RPAD 64                         // fp16 row padded to 64 halves = 128B = 1 full line
#define APAD 48                         // agg fp16 row stride (halves); halves 35..47 stay 0
#define KMMA 80                         // MMA K: [agg 40 | h1 40]
#define NBIN 98                         // dst bins of 1024 nodes
#define BCAP 36864                      // slots per bin (mean 32.8k + 22 sigma)
#define BIN_BLK (N_EDGES / 4 / 256)     // 3125 (4 edges/thread)
#define CONV_BLK (N_NODES * 32 / 256)   // 12500
#define W2_BLK 20                       // 128*80/2 half2 = 5120 -> 20 blocks

// ---------------- device scratch (zero-initialized at load) ----------------
__device__ int    d_off[N_NODES + 1];
__device__ int    d_bin_cur[NBIN];       // bin fill levels; reset by agg (idempotent)
__device__ unsigned long long d_ebuf[(long)NBIN * BCAP];  // (dst<<32|src) per bin
__device__ int    d_csr_src[N_EDGES];    // PRESCALED: src * 8 (uint4-row units)
__device__ __half d_a2[N_NODES * APAD];  // fp16 agg rows; halves 35..47 zero
__device__ __half d_xh[N_NODES * RPAD];  // 128B-aligned fp16 feature rows; pads 35..63 zero
__device__ __half d_w2h[F2 * KMMA];      // fp16 W2^T rows: [Wl2 35|0 5|Wr2 35|0 5]
__device__ int    d_gmax[N_GRAPHS * F2];

#define FMA_F32X2(d, a, b, c) \
    asm("fma.rn.f32x2 %0, %1, %2, %3;" : "=l"(d) : "l"(a), "l"(b), "l"(c))
#define PACK_F32X2(out, lo, hi) \
    asm("mov.b64 %0, {%1, %2};" : "=l"(out) : "f"(lo), "f"(hi))
#define UNPACK_F32X2(lo, hi, in) \
    asm("mov.b64 {%0, %1}, %2;" : "=f"(lo), "=f"(hi) : "l"(in))

__device__ __forceinline__ int fkey(float f) {
    int i = __float_as_int(f);
    return i >= 0 ? i : (i ^ 0x7FFFFFFF);
}

__device__ __forceinline__ unsigned hadd2u(unsigned a, unsigned b) {
    unsigned r;
    asm("add.rn.f16x2 %0, %1, %2;" : "=r"(r) : "r"(a), "r"(b));
    return r;
}

// m16n8k16 fp16 MMA, fp32 accumulate (row-major A, col-major B)
__device__ __forceinline__ void mma16816(float* d, const unsigned* a, const unsigned* b) {
    asm volatile(
        "mma.sync.aligned.m16n8k16.row.col.f32.f16.f16.f32 "
        "{%0,%1,%2,%3}, {%4,%5,%6,%7}, {%8,%9}, {%0,%1,%2,%3};\n"
        : "+f"(d[0]), "+f"(d[1]), "+f"(d[2]), "+f"(d[3])
        : "r"(a[0]), "r"(a[1]), "r"(a[2]), "r"(a[3]), "r"(b[0]), "r"(b[1]));
}

// ---------------- K0: conv(x -> fp16 rows) + gmax reset + W2 fp16 prep ----------------
__global__ void pre_kernel(const float* __restrict__ x,
                           const float* __restrict__ Wl2, const float* __restrict__ Wr2) {
    int b = blockIdx.x, t = threadIdx.x;
    if (b < CONV_BLK) {
        int i = b * 256 + t;
        if (i < N_GRAPHS * F2) d_gmax[i] = (int)0x807FFFFFu;   // fkey(-inf)
        int n = i >> 5, c = i & 31;
        int f0 = 2 * c, f1 = 2 * c + 1;
        float v0 = (f0 < F1) ? x[n * F1 + f0] : 0.f;
        float v1 = (f1 < F1) ? x[n * F1 + f1] : 0.f;
        ((__half2*)d_xh)[i] = __floats2half2_rn(v0, v1);
    } else {
        int i = (b - CONV_BLK) * 256 + t;           // half2 slot in d_w2h
        if (i < F2 * KMMA / 2) {
            int h0 = 2 * i;
            int n = h0 / KMMA, k = h0 - n * KMMA;   // k even, k+1 same row
            float v0 = (k < F1) ? Wl2[k * F2 + n]
                     : ((k >= 40 && k < 40 + F1) ? Wr2[(k - 40) * F2 + n] : 0.f);
            int k1 = k + 1;
            float v1 = (k1 < F1) ? Wl2[k1 * F2 + n]
                     : ((k1 >= 40 && k1 < 40 + F1) ? Wr2[(k1 - 40) * F2 + n] : 0.f);
            ((__half2*)d_w2h)[i] = __floats2half2_rn(v0, v1);
        }
    }
}

// ---------------- K1: bin pass — scatter (dst,src) records into 98 dst-range bins ----------------
__global__ __launch_bounds__(256) void bin_kernel(const int* __restrict__ src,
                                                  const int* __restrict__ dst) {
    __shared__ int hist[NBIN];
    __shared__ int sbase[NBIN];
    const int t = threadIdx.x;
    if (t < NBIN) hist[t] = 0;
    __syncthreads();

    const int i = blockIdx.x * 256 + t;              // int4 slot
    int4 s4 = __ldg(&((const int4*)src)[i]);
    int4 d4 = __ldg(&((const int4*)dst)[i]);
    int b0 = d4.x >> 10, b1 = d4.y >> 10, b2 = d4.z >> 10, b3 = d4.w >> 10;
    int r0 = atomicAdd(&hist[b0], 1);
    int r1 = atomicAdd(&hist[b1], 1);
    int r2 = atomicAdd(&hist[b2], 1);
    int r3 = atomicAdd(&hist[b3], 1);
    __syncthreads();

    if (t < NBIN && hist[t] > 0) sbase[t] = atomicAdd(&d_bin_cur[t], hist[t]);
    __syncthreads();

    d_ebuf[(long)b0 * BCAP + sbase[b0] + r0] = ((unsigned long long)(unsigned)d4.x << 32) | (unsigned)s4.x;
    d_ebuf[(long)b1 * BCAP + sbase[b1] + r1] = ((unsigned long long)(unsigned)d4.y << 32) | (unsigned)s4.y;
    d_ebuf[(long)b2 * BCAP + sbase[b2] + r2] = ((unsigned long long)(unsigned)d4.z << 32) | (unsigned)s4.z;
    d_ebuf[(long)b3 * BCAP + sbase[b3] + r3] = ((unsigned long long)(unsigned)d4.w << 32) | (unsigned)s4.w;
}

// ---------------- K2: sort pass — per-bin counting sort (smem atomics) + d_off ----------------
__global__ __launch_bounds__(1024) void sort_kernel() {
    __shared__ int cnt[1024];
    __shared__ int sws[32];
    __shared__ int sbins[NBIN];
    __shared__ int sbb;
    const int b = blockIdx.x, t = threadIdx.x;
    const int lane = t & 31, wid = t >> 5;

    cnt[t] = 0;
    if (t < NBIN) sbins[t] = d_bin_cur[t];
    __syncthreads();
    if (t == 0) {
        int s = 0;
        for (int j = 0; j < b; j++) s += sbins[j];
        sbb = s;
    }
    const int n_e = sbins[b];
    const unsigned long long* __restrict__ ebuf = d_ebuf + (long)b * BCAP;

    for (int i = t; i < n_e; i += 1024) {
        int ln = (int)(ebuf[i] >> 32) - (b << 10);
        atomicAdd(&cnt[ln], 1);
    }
    __syncthreads();

    const int v = cnt[t];
    int incl = v;
#pragma unroll
    for (int o = 1; o < 32; o <<= 1) {
        int y = __shfl_up_sync(0xffffffffu, incl, o);
        if (lane >= o) incl += y;
    }
    if (lane == 31) sws[wid] = incl;
    __syncthreads();
    if (t < 32) {
        int xv = sws[t], xi = xv;
#pragma unroll
        for (int o = 1; o < 32; o <<= 1) {
            int y = __shfl_up_sync(0xffffffffu, xi, o);
            if (lane >= o) xi += y;
        }
        sws[t] = xi - xv;
    }
    __syncthreads();
    const int excl = sws[wid] + incl - v;

    const int gn = (b << 10) + t;
    if (gn <= N_NODES) d_off[gn] = sbb + excl;

    __syncthreads();
    cnt[t] = excl;
    __syncthreads();

    for (int i = t; i < n_e; i += 1024) {
        unsigned long long ed = ebuf[i];
        int ln = (int)(ed >> 32) - (b << 10);
        int pos = sbb + atomicAdd(&cnt[ln], 1);
        d_csr_src[pos] = ((int)(unsigned)(ed & 0xffffffffu)) * 8;
    }
}

// ---------------- K3: mean aggregation (R13 form): 4 groups x 8 lanes, HADD2 ----------------
// 8 lanes x 16B cover one 128B row exactly; unpredicated quad loop + predicated tail.
// Also resets d_bin_cur for the next graph replay (idempotent; runs twice).
__global__ __launch_bounds__(256) void agg_kernel() {
    if (blockIdx.x == 0 && threadIdx.x < NBIN) d_bin_cur[threadIdx.x] = 0;
    int w = (blockIdx.x * blockDim.x + threadIdx.x) >> 5;
    int lane = threadIdx.x & 31;
    if (w >= N_NODES) return;
    int g = lane >> 3;           // edge group 0..3
    int p = lane & 7;            // 16B slice -> halves 8p..8p+7
    int beg = d_off[w], end = d_off[w + 1];
    int deg = end - beg;

    unsigned a0 = 0u, a1 = 0u, a2 = 0u, a3 = 0u;   // 4x half2 accumulators

    const uint4* __restrict__ xh4 = (const uint4*)d_xh;   // row = 8 uint4
    const int* __restrict__ csr = d_csr_src;              // prescaled (*8)

    int e = beg + g;
    int nq = deg >> 2;
#pragma unroll 4
    for (int q = 0; q < nq; q++, e += 4) {                // unpredicated main loop
        int s = __ldg(&csr[e]);
        uint4 v = __ldg(&xh4[s + p]);
        a0 = hadd2u(a0, v.x);
        a1 = hadd2u(a1, v.y);
        a2 = hadd2u(a2, v.z);
        a3 = hadd2u(a3, v.w);
    }
    int rem = deg & 3;
    if (g < rem) {                                        // predicated tail (<=3 edges)
        int s = __ldg(&csr[e]);
        uint4 v = __ldg(&xh4[s + p]);
        a0 = hadd2u(a0, v.x);
        a1 = hadd2u(a1, v.y);
        a2 = hadd2u(a2, v.z);
        a3 = hadd2u(a3, v.w);
    }

    // butterfly-reduce the 4 edge groups (xor 8, xor 16)
    a0 = hadd2u(a0, __shfl_xor_sync(0xffffffffu, a0, 8));
    a1 = hadd2u(a1, __shfl_xor_sync(0xffffffffu, a1, 8));
    a2 = hadd2u(a2, __shfl_xor_sync(0xffffffffu, a2, 8));
    a3 = hadd2u(a3, __shfl_xor_sync(0xffffffffu, a3, 8));
    a0 = hadd2u(a0, __shfl_xor_sync(0xffffffffu, a0, 16));
    a1 = hadd2u(a1, __shfl_xor_sync(0xffffffffu, a1, 16));
    a2 = hadd2u(a2, __shfl_xor_sync(0xffffffffu, a2, 16));
    a3 = hadd2u(a3, __shfl_xor_sync(0xffffffffu, a3, 16));

    if (lane < 5) {
        float inv = 1.0f / fmaxf((float)deg, 1.0f);
        float2 f0 = __half22float2(*(__half2*)&a0);
        float2 f1 = __half22float2(*(__half2*)&a1);
        float2 f2 = __half22float2(*(__half2*)&a2);
        float2 f3 = __half22float2(*(__half2*)&a3);
        __half2 h0 = __floats2half2_rn(f0.x * inv, f0.y * inv);
        __half2 h1 = __floats2half2_rn(f1.x * inv, f1.y * inv);
        __half2 h2 = __floats2half2_rn(f2.x * inv, f2.y * inv);
        __half2 h3 = __floats2half2_rn(f3.x * inv, f3.y * inv);
        uint4 u;
        u.x = *(unsigned*)&h0; u.y = *(unsigned*)&h1;
        u.z = *(unsigned*)&h2; u.w = *(unsigned*)&h3;
        ((uint4*)(d_a2 + (long)w * APAD))[lane] = u;   // halves 0..39 (35..39 zeros)
    }
}

// ---------------- K4: lin1 fp32 FFMA2, out = relu([agg|x] @ W1 + b1) -> fp16 h1 rows ----------------
__global__ __launch_bounds__(256) void lin1_kernel(
    const float* __restrict__ xin, const float* __restrict__ Wl,
    const float* __restrict__ bl, const float* __restrict__ Wr)
{
    __shared__ __align__(16) float sAT[2 * F1][36];
    __shared__ float sW[2 * F1 * F1];
    __shared__ float sbl[F1];

    const int tid = threadIdx.x;
    const int jt = tid & 31;
    const int mt = tid >> 5;
    const int base_n = blockIdx.x * 32;

    for (int idx = tid; idx < 2 * F1 * F1; idx += 256) {
        int k = idx / F1, j = idx - k * F1;
        sW[idx] = (k < F1) ? Wl[k * F1 + j] : Wr[(k - F1) * F1 + j];
    }
    if (tid < F1) sbl[tid] = bl[tid];
    for (int idx = tid; idx < 32 * F1; idx += 256) {
        int m = idx & 31, k = idx >> 5;
        long n = base_n + m;
        sAT[k][m]      = __half2float(d_a2[n * APAD + k]);
        sAT[k + F1][m] = xin[n * F1 + k];
    }
    __syncthreads();

    unsigned long long acc2[2][2];
#pragma unroll
    for (int p = 0; p < 2; p++)
#pragma unroll
        for (int c = 0; c < 2; c++) acc2[p][c] = 0ULL;

#pragma unroll 2
    for (int k = 0; k < 2 * F1; k++) {
        float4 a4 = *(const float4*)&sAT[k][mt * 4];
        unsigned long long a01, a23;
        PACK_F32X2(a01, a4.x, a4.y);
        PACK_F32X2(a23, a4.z, a4.w);
#pragma unroll
        for (int c = 0; c < 2; c++) {
            int j = jt + 32 * c;
            float w = (j < F1) ? sW[k * F1 + j] : 0.f;
            unsigned long long ww;
            PACK_F32X2(ww, w, w);
            FMA_F32X2(acc2[0][c], a01, ww, acc2[0][c]);
            FMA_F32X2(acc2[1][c], a23, ww, acc2[1][c]);
        }
    }

    const int n0 = base_n + mt * 4;
    float v[4];
#pragma unroll
    for (int c = 0; c < 2; c++) {
        int j = jt + 32 * c;
        if (j < F1) {
            UNPACK_F32X2(v[0], v[1], acc2[0][c]);
            UNPACK_F32X2(v[2], v[3], acc2[1][c]);
#pragma unroll
            for (int r = 0; r < 4; r++) {
                float o = fmaxf(v[r] + sbl[j], 0.f);
                d_xh[(long)(n0 + r) * RPAD + j] = __float2half(o);
            }
        }
    }
}

// ---------------- K6: lin2 + max-pool: HMMA m16n8k16, K=80, vectorized fills ----------------
__global__ __launch_bounds__(256) void mma_pool_kernel(
    const float* __restrict__ bl, const int* __restrict__ batch)
{
    __shared__ __align__(16) __half sA[64 * 88];
    __shared__ __align__(16) __half sB[128 * 88];
    __shared__ float sbl[F2];
    __shared__ int   sgm[F2];

    const int tid = threadIdx.x;
    const int w = tid >> 5;
    const int lane = tid & 31;
    const int gid = lane >> 2;
    const int tig = lane & 3;
    const int base = blockIdx.x * 64;

    // sA: [agg 40h | h1 40h] per row, 10 uint4 loads per row
    const uint4* __restrict__ a2v = (const uint4*)d_a2;   // row = 6 uint4 (use first 5)
    const uint4* __restrict__ xhv = (const uint4*)d_xh;   // row = 8 uint4 (use first 5)
    for (int i = tid; i < 64 * 10; i += 256) {
        int m = i / 10, j = i - (i / 10) * 10;
        long n = base + m;
        uint4 v = make_uint4(0u, 0u, 0u, 0u);
        if (n < N_NODES) v = (j < 5) ? a2v[n * 6 + j] : xhv[n * 8 + (j - 5)];
        *(uint4*)&sA[m * 88 + j * 8] = v;
    }
    // sB from prepped fp16 W2 table: 10 uint4 per row
    const uint4* __restrict__ wv = (const uint4*)d_w2h;   // row = 10 uint4
    for (int i = tid; i < 128 * 10; i += 256) {
        int n = i / 10, j = i - (i / 10) * 10;
        *(uint4*)&sB[n * 88 + j * 8] = wv[n * 10 + j];
    }
    if (tid < F2) { sbl[tid] = bl[tid]; sgm[tid] = (int)0x80000000; }
    __syncthreads();

    const int wm = w & 3;
    const int wn = (w >> 2) * 8;
    float acc[8][4];
#pragma unroll
    for (int nt = 0; nt < 8; nt++)
#pragma unroll
        for (int c = 0; c < 4; c++) acc[nt][c] = 0.f;

#pragma unroll
    for (int kc = 0; kc < 5; kc++) {
        const int k0 = kc * 16;
        unsigned a[4];
        const int ra = (wm * 16 + gid) * 88 + k0 + tig * 2;
        a[0] = *(const unsigned*)&sA[ra];
        a[1] = *(const unsigned*)&sA[ra + 8 * 88];
        a[2] = *(const unsigned*)&sA[ra + 8];
        a[3] = *(const unsigned*)&sA[ra + 8 * 88 + 8];
#pragma unroll
        for (int nt = 0; nt < 8; nt++) {
            unsigned b[2];
            const int rb = ((wn + nt) * 8 + gid) * 88 + k0 + tig * 2;
            b[0] = *(const unsigned*)&sB[rb];
            b[1] = *(const unsigned*)&sB[rb + 8];
            mma16816(acc[nt], a, b);
        }
    }

    const int r0 = base + wm * 16 + gid;
    const int r1 = r0 + 8;
    const bool full = (base + 63 < N_NODES);
    const int gfirst = batch[base];
    const bool single = full && (gfirst == batch[base + 63]);

    if (single) {
#pragma unroll
        for (int nt = 0; nt < 8; nt++) {
            int c0 = (wn + nt) * 8 + tig * 2;
            int k0v = max(fkey(acc[nt][0] + sbl[c0]),     fkey(acc[nt][2] + sbl[c0]));
            int k1v = max(fkey(acc[nt][1] + sbl[c0 + 1]), fkey(acc[nt][3] + sbl[c0 + 1]));
            atomicMax(&sgm[c0], k0v);
            atomicMax(&sgm[c0 + 1], k1v);
        }
        __syncthreads();
        if (tid < F2) atomicMax(&d_gmax[gfirst * F2 + tid], sgm[tid]);
    } else {
        int b0 = (r0 < N_NODES) ? batch[r0] : -1;
        int b1 = (r1 < N_NODES) ? batch[r1] : -1;
#pragma unroll
        for (int nt = 0; nt < 8; nt++) {
            int c0 = (wn + nt) * 8 + tig * 2;
            if (b0 >= 0) {
                atomicMax(&d_gmax[b0 * F2 + c0],     fkey(acc[nt][0] + sbl[c0]));
                atomicMax(&d_gmax[b0 * F2 + c0 + 1], fkey(acc[nt][1] + sbl[c0 + 1]));
            }
            if (b1 >= 0) {
                atomicMax(&d_gmax[b1 * F2 + c0],     fkey(acc[nt][2] + sbl[c0]));
                atomicMax(&d_gmax[b1 * F2 + c0 + 1], fkey(acc[nt][3] + sbl[c0 + 1]));
            }
        }
    }
}

// ---------------- K7: FC head ----------------
__global__ __launch_bounds__(128) void head_kernel(
    const float* __restrict__ Wg1, const float* __restrict__ bg1,
    const float* __restrict__ Wg2, const float* __restrict__ bg2,
    const float* __restrict__ Wo,  const float* __restrict__ bo,
    float* __restrict__ out)
{
    int g = blockIdx.x, j = threadIdx.x;
    __shared__ float r0[F2], r1[F2];
    __shared__ float wred[4];
    int key = d_gmax[g * F2 + j];
    key = key >= 0 ? key : (key ^ 0x7FFFFFFF);
    r0[j] = __int_as_float(key);
    __syncthreads();
    float acc = bg1[j];
#pragma unroll 8
    for (int k = 0; k < F2; k++) acc += r0[k] * Wg1[k * F2 + j];
    r1[j] = fmaxf(acc, 0.f);
    __syncthreads();
    acc = bg2[j];
#pragma unroll 8
    for (int k = 0; k < F2; k++) acc += r1[k] * Wg2[k * F2 + j];
    float v = fmaxf(acc, 0.f) * Wo[j];
#pragma unroll
    for (int s = 16; s > 0; s >>= 1) v += __shfl_down_sync(0xffffffffu, v, s);
    if ((j & 31) == 0) wred[j >> 5] = v;
    __syncthreads();
    if (j == 0) out[g] = wred[0] + wred[1] + wred[2] + wred[3] + bo[0];
}

// ---------------- launcher (8 kernels; agg1 at capture index 3) ----------------
extern "C" void kernel_launch(void* const* d_in, const int* in_sizes, int n_in,
                              void* d_out, int out_size) {
    const float* x    = (const float*)d_in[0];
    const int*   ei   = (const int*)d_in[1];
    const int*   bat  = (const int*)d_in[2];
    const float* Wl1  = (const float*)d_in[3];
    const float* bl1  = (const float*)d_in[4];
    const float* Wr1  = (const float*)d_in[5];
    const float* Wl2  = (const float*)d_in[6];
    const float* bl2  = (const float*)d_in[7];
    const float* Wr2  = (const float*)d_in[8];
    const float* Wg1  = (const float*)d_in[9];
    const float* bg1  = (const float*)d_in[10];
    const float* Wg2  = (const float*)d_in[11];
    const float* bg2  = (const float*)d_in[12];
    const float* Wo   = (const float*)d_in[13];
    const float* bo   = (const float*)d_in[14];
    float* out = (float*)d_out;

    const int* src = ei;
    const int* dst = ei + N_EDGES;

    pre_kernel<<<CONV_BLK + W2_BLK, 256>>>(x, Wl2, Wr2);                // 0
    bin_kernel<<<BIN_BLK, 256>>>(src, dst);                             // 1
    sort_kernel<<<NBIN, 1024>>>();                                      // 2

    agg_kernel<<<(N_NODES * 32 + 255) / 256, 256>>>();                  // 3 <- profiled
    lin1_kernel<<<N_NODES / 32, 256>>>(x, Wl1, bl1, Wr1);               // 4

    agg_kernel<<<(N_NODES * 32 + 255) / 256, 256>>>();                  // 5
    mma_pool_kernel<<<(N_NODES + 63) / 64, 256>>>(bl2, bat);            // 6

    head_kernel<<<N_GRAPHS, F2>>>(Wg1, bg1, Wg2, bg2, Wo, bo, out);     // 7
}